// round 11
// baseline (speedup 1.0000x reference)
#include <cuda_runtime.h>
#include <cuda_fp16.h>
#include <math.h>

#define N_MAX 100000
#define E_MAX 1600000

// ---------------- scratch (device globals; allocation-free) ----------------
__device__ float g_deg [N_MAX];                        // in-degree (0-based; +1 at use)
__device__ float g_dinv[N_MAX];                        // rsqrt(deg+1)
__device__ __align__(16) float   g_y1  [N_MAX * 8];    // x * dinv (pre-scaled src msg)
__device__ __align__(16) float   g_accx[N_MAX * 8];    // Σ y1 over in-nbrs + self
__device__ __align__(16) __half2 g_y2h [N_MAX * 8];    // h2 * dinv, fp16 (16 feats/node)
__device__ __align__(16) float   g_acc2[N_MAX * 16];   // Σ y2 over in-nbrs + self (fp32)

// ---------------- degree (g_deg zeroed by memset before this) ----------------
__global__ void k_count(const int* __restrict__ dst, int e) {
    int i = blockIdx.x * blockDim.x + threadIdx.x;
    if (i < e) atomicAdd(&g_deg[__ldg(dst + i)], 1.0f);   // RED
}

// dinv, y1 = x*dinv, acc_x init = y1 (self term). 2 lanes/node, float4 each.
__global__ void k_prep(const float* __restrict__ x, int n) {
    int t = blockIdx.x * blockDim.x + threadIdx.x;
    int node = t >> 1;
    if (node >= n) return;
    int g = t & 1;
    float di = rsqrtf(g_deg[node] + 1.0f);                // +1 = self-loop
    if (g == 0) g_dinv[node] = di;
    float4 xv = __ldg(reinterpret_cast<const float4*>(x + node * 8) + g);
    float4 yv = make_float4(xv.x * di, xv.y * di, xv.z * di, xv.w * di);
    *(reinterpret_cast<float4*>(g_y1 + node * 8) + g) = yv;
    *(reinterpret_cast<float4*>(g_accx + node * 8) + g) = yv;
}

// layer-1 scatter on raw input features (8-dim): one thread per edge
__global__ void k_edge1(const int* __restrict__ src, const int* __restrict__ dst, int e) {
    int i = blockIdx.x * blockDim.x + threadIdx.x;
    if (i >= e) return;
    int s = __ldg(src + i);
    int d = __ldg(dst + i);
    const float4* yp = reinterpret_cast<const float4*>(g_y1 + s * 8);
    float4 v0 = __ldg(yp);
    float4 v1 = __ldg(yp + 1);
    float4* ap = reinterpret_cast<float4*>(g_accx + d * 8);
    atomicAdd(ap,     v0);
    atomicAdd(ap + 1, v1);
}

// per node: a = acc_x*dinv, v = relu(a@W1+b1), h2 = v@W2,
// emit y2 = h2*dinv as fp16 (read path) and fp32 into acc2 (self term).
__global__ void k_mid(const float* __restrict__ W1, const float* __restrict__ b1,
                      const float* __restrict__ W2, int n) {
    __shared__ float sW1[8 * 32];
    __shared__ float sW2[32 * 16];
    __shared__ float sb1[32];
    int tid = threadIdx.x;
    if (tid < 256) sW1[tid] = __ldg(W1 + tid);
    sW2[tid] = __ldg(W2 + tid);
    sW2[tid + 256] = __ldg(W2 + tid + 256);
    if (tid < 32) sb1[tid] = __ldg(b1 + tid);
    __syncthreads();

    int node = blockIdx.x * blockDim.x + tid;
    if (node >= n) return;
    float di = g_dinv[node];

    float a[8];
    float4 a0 = *reinterpret_cast<const float4*>(g_accx + node * 8);
    float4 a1 = *(reinterpret_cast<const float4*>(g_accx + node * 8) + 1);
    a[0] = a0.x * di; a[1] = a0.y * di; a[2] = a0.z * di; a[3] = a0.w * di;
    a[4] = a1.x * di; a[5] = a1.y * di; a[6] = a1.z * di; a[7] = a1.w * di;

    float v[32];
#pragma unroll
    for (int c = 0; c < 32; c++) {
        float s = sb1[c];
#pragma unroll
        for (int k = 0; k < 8; k++) s = fmaf(a[k], sW1[k * 32 + c], s);
        v[c] = fmaxf(s, 0.f);
    }

    float o[16];
#pragma unroll
    for (int c = 0; c < 16; c++) {
        float s = 0.f;
#pragma unroll
        for (int k = 0; k < 32; k++) s = fmaf(v[k], sW2[k * 16 + c], s);
        o[c] = s * di;                               // pre-scale by dinv
    }

    // fp32 self term into acc2
#pragma unroll
    for (int q = 0; q < 4; q++)
        *(reinterpret_cast<float4*>(g_acc2 + node * 16) + q) =
            make_float4(o[q * 4], o[q * 4 + 1], o[q * 4 + 2], o[q * 4 + 3]);

    // fp16 message row (32B)
    __align__(16) __half2 hv[8];
#pragma unroll
    for (int k = 0; k < 8; k++) hv[k] = __floats2half2_rn(o[2 * k], o[2 * k + 1]);
    float4* yp = reinterpret_cast<float4*>(g_y2h + node * 8);
    yp[0] = *reinterpret_cast<float4*>(&hv[0]);
    yp[1] = *reinterpret_cast<float4*>(&hv[4]);
}

// layer-2 scatter: 4 lanes/edge; lane reads 8B fp16, REDs 16B fp32
__global__ void k_edge2(const int* __restrict__ src, const int* __restrict__ dst, int e) {
    int t = blockIdx.x * blockDim.x + threadIdx.x;
    int ed = t >> 2;
    if (ed >= e) return;
    int g = t & 3;
    int s = __ldg(src + ed);
    int d = __ldg(dst + ed);
    float2 raw = __ldg(reinterpret_cast<const float2*>(g_y2h + s * 8) + g);
    __half2 h0 = *reinterpret_cast<__half2*>(&raw.x);
    __half2 h1 = *reinterpret_cast<__half2*>(&raw.y);
    float2 f0 = __half22float2(h0);
    float2 f1 = __half22float2(h1);
    atomicAdd(reinterpret_cast<float4*>(g_acc2 + d * 16) + g,
              make_float4(f0.x, f0.y, f1.x, f1.y));
}

// out = sigmoid(relu(acc2*dinv + b2) @ Wfc + bfc)
__global__ void k_fin(const float* __restrict__ b2, const float* __restrict__ Wfc,
                      const float* __restrict__ bfc, float* __restrict__ out, int n) {
    __shared__ float swf[16];
    __shared__ float sb[16];
    __shared__ float sbf;
    int tid = threadIdx.x;
    if (tid < 16) { swf[tid] = __ldg(Wfc + tid); sb[tid] = __ldg(b2 + tid); }
    if (tid == 0) sbf = __ldg(bfc);
    __syncthreads();

    int i = blockIdx.x * blockDim.x + tid;
    if (i >= n) return;
    float di = g_dinv[i];
    float s = sbf;
#pragma unroll
    for (int q = 0; q < 4; q++) {
        float4 a = *(reinterpret_cast<const float4*>(g_acc2 + i * 16) + q);
        s = fmaf(fmaxf(a.x * di + sb[q * 4 + 0], 0.f), swf[q * 4 + 0], s);
        s = fmaf(fmaxf(a.y * di + sb[q * 4 + 1], 0.f), swf[q * 4 + 1], s);
        s = fmaf(fmaxf(a.z * di + sb[q * 4 + 2], 0.f), swf[q * 4 + 2], s);
        s = fmaf(fmaxf(a.w * di + sb[q * 4 + 3], 0.f), swf[q * 4 + 3], s);
    }
    out[i] = 1.0f / (1.0f + expf(-s));
}

// ---------------- launch ----------------
extern "C" void kernel_launch(void* const* d_in, const int* in_sizes, int n_in,
                              void* d_out, int out_size) {
    const float* x   = (const float*)d_in[0];
    const int*   ei  = (const int*)d_in[1];
    const float* W1  = (const float*)d_in[2];
    const float* b1  = (const float*)d_in[3];
    const float* W2  = (const float*)d_in[4];
    const float* b2  = (const float*)d_in[5];
    const float* Wfc = (const float*)d_in[6];
    const float* bfc = (const float*)d_in[7];
    float* out = (float*)d_out;

    int n = in_sizes[0] / 8;        // 100000
    int e = in_sizes[1] / 2;        // 1600000
    const int* src = ei;
    const int* dst = ei + e;

    const int B = 256;
    int gn = (n + B - 1) / B;

    void* degp = nullptr;
    cudaGetSymbolAddress(&degp, g_deg);
    cudaMemsetAsync(degp, 0, (size_t)n * sizeof(float));

    k_count<<<(e + 511) / 512, 512>>>(dst, e);
    k_prep <<<(n * 2 + B - 1) / B, B>>>(x, n);
    k_edge1<<<(e + B - 1) / B, B>>>(src, dst, e);
    k_mid  <<<gn, B>>>(W1, b1, W2, n);
    k_edge2<<<(int)(((long long)e * 4 + B - 1) / B), B>>>(src, dst, e);
    k_fin  <<<gn, B>>>(b2, Wfc, bfc, out, n);
}